// round 3
// baseline (speedup 1.0000x reference)
#include <cuda_runtime.h>
#include <cstdint>

#define N_NODES 100000
#define N_EDGES 1250000
#define D 64

// Scratch (static device globals — no allocation allowed)
__device__ float g_agg[(size_t)N_NODES * D];   // 25.6 MB aggregation buffer
__device__ int   g_deg[N_NODES];
__device__ int   g_off[N_NODES + 1];
__device__ int   g_cur[N_NODES];
__device__ int   g_srcs[N_EDGES];
__device__ int   g_is64;

// ---------------------------------------------------------------------------
// Detect int64 vs int32 edge_index layout (odd 32-bit words all zero => i64).
// ---------------------------------------------------------------------------
__global__ void detect_kernel(const unsigned* __restrict__ ei) {
    if (threadIdx.x == 0 && blockIdx.x == 0) {
        int all0 = 1;
        #pragma unroll 1
        for (int i = 0; i < 64; i++) {
            if (ei[2 * i + 1] != 0u) { all0 = 0; break; }
        }
        g_is64 = all0;
    }
}

__device__ __forceinline__ int load_idx(const void* ei, int pos) {
    if (g_is64) return (int)((const long long*)ei)[pos];
    return ((const int*)ei)[pos];
}

// ---------------------------------------------------------------------------
// CSR build: zero degrees -> histogram over dst -> exclusive scan -> fill
// ---------------------------------------------------------------------------
__global__ void zero_deg_kernel() {
    int i = blockIdx.x * blockDim.x + threadIdx.x;
    if (i < N_NODES) g_deg[i] = 0;
}

__global__ void hist_kernel(const void* __restrict__ ei) {
    int e = blockIdx.x * blockDim.x + threadIdx.x;
    if (e >= N_EDGES) return;
    int d = load_idx(ei, e + N_EDGES);
    atomicAdd(&g_deg[d], 1);
}

// Single-block exclusive scan of g_deg into g_off (and g_cur cursor copy).
__global__ void scan_kernel() {
    const int CHUNK = (N_NODES + 1023) / 1024;   // 98
    __shared__ int wsum[32];
    int t = threadIdx.x;
    int start = t * CHUNK;

    int sum = 0;
    for (int i = 0; i < CHUNK; i++) {
        int idx = start + i;
        if (idx < N_NODES) sum += g_deg[idx];
    }
    int lane = t & 31, wid = t >> 5;
    int v = sum;
    #pragma unroll
    for (int o = 1; o < 32; o <<= 1) {
        int n = __shfl_up_sync(0xffffffffu, v, o);
        if (lane >= o) v += n;
    }
    if (lane == 31) wsum[wid] = v;
    __syncthreads();
    if (wid == 0) {
        int w = wsum[lane];
        #pragma unroll
        for (int o = 1; o < 32; o <<= 1) {
            int n = __shfl_up_sync(0xffffffffu, w, o);
            if (lane >= o) w += n;
        }
        wsum[lane] = w;
    }
    __syncthreads();
    int excl = v - sum + (wid > 0 ? wsum[wid - 1] : 0);

    int run = excl;
    for (int i = 0; i < CHUNK; i++) {
        int idx = start + i;
        if (idx < N_NODES) {
            g_off[idx] = run;
            g_cur[idx] = run;
            run += g_deg[idx];
        }
    }
    if (t == 1023) g_off[N_NODES] = run;   // thread 1023 has no elements: run == total
}

__global__ void fill_kernel(const void* __restrict__ ei) {
    int e = blockIdx.x * blockDim.x + threadIdx.x;
    if (e >= N_EDGES) return;
    int s = load_idx(ei, e);
    int d = load_idx(ei, e + N_EDGES);
    int pos = atomicAdd(&g_cur[d], 1);
    g_srcs[pos] = s;
}

// ---------------------------------------------------------------------------
// Gather-aggregate: g_agg[i] = sum over incoming edges of h[src].
// 16 lanes per node, each owning one float4 chunk. No atomics.
// ---------------------------------------------------------------------------
__global__ void gather_kernel(const float* __restrict__ h) {
    int t = blockIdx.x * blockDim.x + threadIdx.x;
    int node = t >> 4;
    int c = t & 15;
    if (node >= N_NODES) return;

    int beg = __ldg(&g_off[node]);
    int end = __ldg(&g_off[node + 1]);

    float4 acc = make_float4(0.f, 0.f, 0.f, 0.f);
    #pragma unroll 4
    for (int e = beg; e < end; e++) {
        int s = __ldg(&g_srcs[e]);
        float4 v = *reinterpret_cast<const float4*>(h + (size_t)s * D + c * 4);
        acc.x += v.x; acc.y += v.y; acc.z += v.z; acc.w += v.w;
    }
    *reinterpret_cast<float4*>(g_agg + (size_t)node * D + c * 4) = acc;
}

// ---------------------------------------------------------------------------
// Linear: out[i][j] = sum_k g_agg[i][k] * W[j][k] + b[j]
// 64x64 output tile per block, 4x4 register tile per thread, fma.rn.f32x2
// (FFMA2) with k-pairs packed directly by ulonglong2 smem loads.
// acc.lo accumulates even-k products, acc.hi odd-k; reduced at the end.
// ---------------------------------------------------------------------------
#define SROW 68   // padded smem row stride in floats (272B: 16B-aligned, bank-safe)

__global__ void linear_kernel(float* __restrict__ out,
                              const float* __restrict__ W,
                              const float* __restrict__ b) {
    __shared__ __align__(16) float As[64 * SROW];
    __shared__ __align__(16) float Ws[64 * SROW];

    const int t = threadIdx.x;           // 256 threads
    const int row0 = blockIdx.x * 64;

    // Stage W [64][64] and A [64][64] into padded smem (float4 loads)
    #pragma unroll
    for (int i = t; i < 64 * 16; i += 256) {
        int j = i >> 4, k4 = i & 15;
        *reinterpret_cast<float4*>(&Ws[j * SROW + k4 * 4]) =
            reinterpret_cast<const float4*>(W)[j * 16 + k4];
    }
    #pragma unroll
    for (int i = t; i < 64 * 16; i += 256) {
        int r = i >> 4, k4 = i & 15;
        int row = row0 + r;
        float4 v = make_float4(0.f, 0.f, 0.f, 0.f);
        if (row < N_NODES)
            v = reinterpret_cast<const float4*>(g_agg)[(size_t)row * 16 + k4];
        *reinterpret_cast<float4*>(&As[r * SROW + k4 * 4]) = v;
    }
    __syncthreads();

    const int tx = t & 15;   // cols: tx + 16*ji  (stride-16 -> conflict-free W LDS)
    const int ty = t >> 4;   // rows: ty*4 + ri

    unsigned long long acc[4][4];
    #pragma unroll
    for (int ri = 0; ri < 4; ri++)
        #pragma unroll
        for (int ji = 0; ji < 4; ji++) acc[ri][ji] = 0ull;

    #pragma unroll 4
    for (int k4 = 0; k4 < 16; k4++) {
        ulonglong2 a[4], w[4];
        #pragma unroll
        for (int ri = 0; ri < 4; ri++)
            a[ri] = *reinterpret_cast<const ulonglong2*>(&As[(ty * 4 + ri) * SROW + k4 * 4]);
        #pragma unroll
        for (int ji = 0; ji < 4; ji++)
            w[ji] = *reinterpret_cast<const ulonglong2*>(&Ws[(tx + 16 * ji) * SROW + k4 * 4]);
        #pragma unroll
        for (int ri = 0; ri < 4; ri++)
            #pragma unroll
            for (int ji = 0; ji < 4; ji++) {
                asm("fma.rn.f32x2 %0, %1, %2, %0;"
                    : "+l"(acc[ri][ji]) : "l"(a[ri].x), "l"(w[ji].x));
                asm("fma.rn.f32x2 %0, %1, %2, %0;"
                    : "+l"(acc[ri][ji]) : "l"(a[ri].y), "l"(w[ji].y));
            }
    }

    float bj[4];
    #pragma unroll
    for (int ji = 0; ji < 4; ji++) bj[ji] = __ldg(&b[tx + 16 * ji]);

    #pragma unroll
    for (int ri = 0; ri < 4; ri++) {
        int row = row0 + ty * 4 + ri;
        if (row < N_NODES) {
            #pragma unroll
            for (int ji = 0; ji < 4; ji++) {
                float lo, hi;
                asm("mov.b64 {%0, %1}, %2;" : "=f"(lo), "=f"(hi) : "l"(acc[ri][ji]));
                out[(size_t)row * D + tx + 16 * ji] = lo + hi + bj[ji];
            }
        }
    }
}

// ---------------------------------------------------------------------------
extern "C" void kernel_launch(void* const* d_in, const int* in_sizes, int n_in,
                              void* d_out, int out_size) {
    const float* x  = (const float*)d_in[0];
    const void*  ei = d_in[1];
    const float* W1 = (const float*)d_in[2];
    const float* b1 = (const float*)d_in[3];

    float* out = (float*)d_out;                      // (out, hid) flattened
    float* hid = out + (size_t)N_NODES * D;

    const int EBLK = (N_EDGES + 255) / 256;
    const int NBLK = (N_NODES + 255) / 256;
    const int GBLK = (N_NODES * 16 + 255) / 256;     // 6250
    const int LBLK = (N_NODES + 63) / 64;            // 1563

    detect_kernel<<<1, 1>>>((const unsigned*)ei);

    // CSR build (once; reused by both layers)
    zero_deg_kernel<<<NBLK, 256>>>();
    hist_kernel<<<EBLK, 256>>>(ei);
    scan_kernel<<<1, 1024>>>();
    fill_kernel<<<EBLK, 256>>>(ei);

    // Layer 1: hid = gather(x) @ W1^T + b1
    gather_kernel<<<GBLK, 256>>>(x);
    linear_kernel<<<LBLK, 256>>>(hid, W1, b1);

    // Layer 2: out = gather(hid) @ W1^T + b1
    gather_kernel<<<GBLK, 256>>>(hid);
    linear_kernel<<<LBLK, 256>>>(out, W1, b1);
}

// round 4
// speedup vs baseline: 2.1223x; 2.1223x over previous
#include <cuda_runtime.h>
#include <cstdint>

#define N_NODES 100000
#define N_EDGES 1250000
#define D 64
#define SCAN_BLOCKS ((N_NODES + 255) / 256)   // 391

// Scratch (static device globals — no allocation allowed)
__device__ float g_agg[(size_t)N_NODES * D];   // 25.6 MB aggregation buffer
__device__ int   g_deg[N_NODES];
__device__ int   g_off[N_NODES + 1];
__device__ int   g_cur[N_NODES];
__device__ int   g_srcs[N_EDGES];
__device__ int   g_bsum[SCAN_BLOCKS];
__device__ int   g_boff[SCAN_BLOCKS];
__device__ int   g_is64;

// ---------------------------------------------------------------------------
// Detect int64 vs int32 edge_index layout (odd 32-bit words all zero => i64).
// ---------------------------------------------------------------------------
__global__ void detect_kernel(const unsigned* __restrict__ ei) {
    if (threadIdx.x == 0 && blockIdx.x == 0) {
        int all0 = 1;
        #pragma unroll 1
        for (int i = 0; i < 64; i++) {
            if (ei[2 * i + 1] != 0u) { all0 = 0; break; }
        }
        g_is64 = all0;
    }
}

__device__ __forceinline__ int load_idx(const void* ei, int pos) {
    if (g_is64) return (int)((const long long*)ei)[pos];
    return ((const int*)ei)[pos];
}

// ---------------------------------------------------------------------------
// CSR build: zero -> histogram -> 3-phase parallel scan -> fill
// ---------------------------------------------------------------------------
__global__ void zero_deg_kernel() {
    int i = blockIdx.x * blockDim.x + threadIdx.x;
    if (i < N_NODES) g_deg[i] = 0;
}

__global__ void hist_kernel(const void* __restrict__ ei) {
    int e = blockIdx.x * blockDim.x + threadIdx.x;
    if (e >= N_EDGES) return;
    int d = load_idx(ei, e + N_EDGES);
    atomicAdd(&g_deg[d], 1);
}

// Phase 1: per-block (256-element) sums of g_deg.
__global__ void partial_kernel() {
    __shared__ int ws[8];
    int t = threadIdx.x;
    int idx = blockIdx.x * 256 + t;
    int v = (idx < N_NODES) ? g_deg[idx] : 0;
    #pragma unroll
    for (int o = 16; o > 0; o >>= 1) v += __shfl_down_sync(0xffffffffu, v, o);
    if ((t & 31) == 0) ws[t >> 5] = v;
    __syncthreads();
    if (t == 0) {
        int s = 0;
        #pragma unroll
        for (int i = 0; i < 8; i++) s += ws[i];
        g_bsum[blockIdx.x] = s;
    }
}

// Phase 2: single-block exclusive scan of the 391 block sums.
__global__ void scan_bsums_kernel() {
    __shared__ int ws[16];
    int t = threadIdx.x;           // 512 threads
    int lane = t & 31, wid = t >> 5;
    int v = (t < SCAN_BLOCKS) ? g_bsum[t] : 0;
    int incl = v;
    #pragma unroll
    for (int o = 1; o < 32; o <<= 1) {
        int n = __shfl_up_sync(0xffffffffu, incl, o);
        if (lane >= o) incl += n;
    }
    if (lane == 31) ws[wid] = incl;
    __syncthreads();
    if (wid == 0) {
        int w = (lane < 16) ? ws[lane] : 0;
        #pragma unroll
        for (int o = 1; o < 16; o <<= 1) {
            int n = __shfl_up_sync(0xffffffffu, w, o);
            if (lane >= o) w += n;
        }
        if (lane < 16) ws[lane] = w;
    }
    __syncthreads();
    int excl = incl - v + (wid ? ws[wid - 1] : 0);
    if (t < SCAN_BLOCKS) g_boff[t] = excl;
    if (t == 0) g_off[N_NODES] = N_EDGES;   // every dst lands in some bucket
}

// Phase 3: in-block exclusive scan + block offset -> g_off / g_cur.
__global__ void write_off_kernel() {
    __shared__ int ws[8];
    int t = threadIdx.x;
    int lane = t & 31, wid = t >> 5;
    int idx = blockIdx.x * 256 + t;
    int v = (idx < N_NODES) ? g_deg[idx] : 0;
    int incl = v;
    #pragma unroll
    for (int o = 1; o < 32; o <<= 1) {
        int n = __shfl_up_sync(0xffffffffu, incl, o);
        if (lane >= o) incl += n;
    }
    if (lane == 31) ws[wid] = incl;
    __syncthreads();
    if (wid == 0) {
        int w = (lane < 8) ? ws[lane] : 0;
        #pragma unroll
        for (int o = 1; o < 8; o <<= 1) {
            int n = __shfl_up_sync(0xffffffffu, w, o);
            if (lane >= o) w += n;
        }
        if (lane < 8) ws[lane] = w;
    }
    __syncthreads();
    int excl = incl - v + (wid ? ws[wid - 1] : 0) + g_boff[blockIdx.x];
    if (idx < N_NODES) {
        g_off[idx] = excl;
        g_cur[idx] = excl;
    }
}

__global__ void fill_kernel(const void* __restrict__ ei) {
    int e = blockIdx.x * blockDim.x + threadIdx.x;
    if (e >= N_EDGES) return;
    int s = load_idx(ei, e);
    int d = load_idx(ei, e + N_EDGES);
    int pos = atomicAdd(&g_cur[d], 1);
    g_srcs[pos] = s;
}

// ---------------------------------------------------------------------------
// Gather-aggregate: g_agg[i] = sum over incoming edges of h[src]. No atomics.
// 16 lanes per node, each owning one float4 chunk.
// ---------------------------------------------------------------------------
__global__ void gather_kernel(const float* __restrict__ h) {
    int t = blockIdx.x * blockDim.x + threadIdx.x;
    int node = t >> 4;
    int c = t & 15;
    if (node >= N_NODES) return;

    int beg = __ldg(&g_off[node]);
    int end = __ldg(&g_off[node + 1]);

    float4 acc = make_float4(0.f, 0.f, 0.f, 0.f);
    #pragma unroll 4
    for (int e = beg; e < end; e++) {
        int s = __ldg(&g_srcs[e]);
        float4 v = *reinterpret_cast<const float4*>(h + (size_t)s * D + c * 4);
        acc.x += v.x; acc.y += v.y; acc.z += v.z; acc.w += v.w;
    }
    *reinterpret_cast<float4*>(g_agg + (size_t)node * D + c * 4) = acc;
}

// ---------------------------------------------------------------------------
// Linear: out[i][j] = sum_k g_agg[i][k] * W[j][k] + b[j]
// 64x64 tile per block, 4x4 register tile per thread, fma.rn.f32x2 (FFMA2).
// ---------------------------------------------------------------------------
#define SROW 68   // padded smem row stride in floats

__global__ void linear_kernel(float* __restrict__ out,
                              const float* __restrict__ W,
                              const float* __restrict__ b) {
    __shared__ __align__(16) float As[64 * SROW];
    __shared__ __align__(16) float Ws[64 * SROW];

    const int t = threadIdx.x;           // 256 threads
    const int row0 = blockIdx.x * 64;

    #pragma unroll
    for (int i = t; i < 64 * 16; i += 256) {
        int j = i >> 4, k4 = i & 15;
        *reinterpret_cast<float4*>(&Ws[j * SROW + k4 * 4]) =
            reinterpret_cast<const float4*>(W)[j * 16 + k4];
    }
    #pragma unroll
    for (int i = t; i < 64 * 16; i += 256) {
        int r = i >> 4, k4 = i & 15;
        int row = row0 + r;
        float4 v = make_float4(0.f, 0.f, 0.f, 0.f);
        if (row < N_NODES)
            v = reinterpret_cast<const float4*>(g_agg)[(size_t)row * 16 + k4];
        *reinterpret_cast<float4*>(&As[r * SROW + k4 * 4]) = v;
    }
    __syncthreads();

    const int tx = t & 15;
    const int ty = t >> 4;

    unsigned long long acc[4][4];
    #pragma unroll
    for (int ri = 0; ri < 4; ri++)
        #pragma unroll
        for (int ji = 0; ji < 4; ji++) acc[ri][ji] = 0ull;

    #pragma unroll 4
    for (int k4 = 0; k4 < 16; k4++) {
        ulonglong2 a[4], w[4];
        #pragma unroll
        for (int ri = 0; ri < 4; ri++)
            a[ri] = *reinterpret_cast<const ulonglong2*>(&As[(ty * 4 + ri) * SROW + k4 * 4]);
        #pragma unroll
        for (int ji = 0; ji < 4; ji++)
            w[ji] = *reinterpret_cast<const ulonglong2*>(&Ws[(tx + 16 * ji) * SROW + k4 * 4]);
        #pragma unroll
        for (int ri = 0; ri < 4; ri++)
            #pragma unroll
            for (int ji = 0; ji < 4; ji++) {
                asm("fma.rn.f32x2 %0, %1, %2, %0;"
                    : "+l"(acc[ri][ji]) : "l"(a[ri].x), "l"(w[ji].x));
                asm("fma.rn.f32x2 %0, %1, %2, %0;"
                    : "+l"(acc[ri][ji]) : "l"(a[ri].y), "l"(w[ji].y));
            }
    }

    float bj[4];
    #pragma unroll
    for (int ji = 0; ji < 4; ji++) bj[ji] = __ldg(&b[tx + 16 * ji]);

    #pragma unroll
    for (int ri = 0; ri < 4; ri++) {
        int row = row0 + ty * 4 + ri;
        if (row < N_NODES) {
            #pragma unroll
            for (int ji = 0; ji < 4; ji++) {
                float lo, hi;
                asm("mov.b64 {%0, %1}, %2;" : "=f"(lo), "=f"(hi) : "l"(acc[ri][ji]));
                out[(size_t)row * D + tx + 16 * ji] = lo + hi + bj[ji];
            }
        }
    }
}

// ---------------------------------------------------------------------------
extern "C" void kernel_launch(void* const* d_in, const int* in_sizes, int n_in,
                              void* d_out, int out_size) {
    const float* x  = (const float*)d_in[0];
    const void*  ei = d_in[1];
    const float* W1 = (const float*)d_in[2];
    const float* b1 = (const float*)d_in[3];

    float* out = (float*)d_out;                      // (out, hid) flattened
    float* hid = out + (size_t)N_NODES * D;

    const int EBLK = (N_EDGES + 255) / 256;
    const int NBLK = (N_NODES + 255) / 256;
    const int GBLK = (N_NODES * 16 + 255) / 256;     // 6250
    const int LBLK = (N_NODES + 63) / 64;            // 1563

    detect_kernel<<<1, 1>>>((const unsigned*)ei);

    // CSR build (reused by both layers)
    zero_deg_kernel<<<NBLK, 256>>>();
    hist_kernel<<<EBLK, 256>>>(ei);
    partial_kernel<<<SCAN_BLOCKS, 256>>>();
    scan_bsums_kernel<<<1, 512>>>();
    write_off_kernel<<<SCAN_BLOCKS, 256>>>();
    fill_kernel<<<EBLK, 256>>>(ei);

    // Layer 1: hid = gather(x) @ W1^T + b1
    gather_kernel<<<GBLK, 256>>>(x);
    linear_kernel<<<LBLK, 256>>>(hid, W1, b1);

    // Layer 2: out = gather(hid) @ W1^T + b1
    gather_kernel<<<GBLK, 256>>>(hid);
    linear_kernel<<<LBLK, 256>>>(out, W1, b1);
}